// round 3
// baseline (speedup 1.0000x reference)
#include <cuda_runtime.h>
#include <math.h>

// Problem constants
// B=4, H=W=256, C=96, NH=6, HD=16, WS=8, N=64
// windows per image: 32x32=1024, total 4096
// SCALE = 16^-0.5 = 0.25

#define N_TOK_TOTAL (4*256*256)      // 262144 tokens
#define X_ELEMS     (4*256*256*96)   // 25165824

__device__ float g_x[X_ELEMS];       // ping-pong scratch (100.7 MB)

// -------------------- Attention kernel (one 64-token window per block) --------------------
// smem layout (floats): xs[64*96] | qkv[18*64*16] | wb[96*97] | sc[64*64]
#define ATTN_SMEM_FLOATS (6144 + 18432 + 9312 + 4096)

__global__ void __launch_bounds__(256) attn_kernel(
    const float* __restrict__ xin, float* __restrict__ xout,
    const float* __restrict__ qkvw, const float* __restrict__ qkvb,
    const float* __restrict__ projw, const float* __restrict__ projb,
    const float* __restrict__ rpb,
    const float* __restrict__ g1, const float* __restrict__ bb1,
    int shift)
{
    extern __shared__ float sm[];
    float* xs  = sm;                    // 64 x 96  (LN'd input, later reused as attention context)
    float* qkv = sm + 6144;             // [3][6][64][16]
    float* wb  = sm + 6144 + 18432;     // 96 x 97 weight tile (pitch 97: conflict-free)
    float* sc  = sm + 6144 + 18432 + 9312; // 64 x 64 scores

    const int tid = threadIdx.x;
    const int win = blockIdx.x;
    const int b   = win >> 10;
    const int wi  = win & 1023;
    const int wh  = wi >> 5;
    const int wwn = wi & 31;

    // ---------- load + LayerNorm1 (4 threads per token) ----------
    {
        int t  = tid >> 2;
        int l4 = tid & 3;
        int th = t >> 3, tw = t & 7;
        int hr = wh*8 + th, wr = wwn*8 + tw;                 // shifted-image coords
        int h0 = (hr + shift) & 255, w0 = (wr + shift) & 255; // original coords (roll -shift)
        const float* xrow = xin + ((size_t)b*65536 + (size_t)h0*256 + w0)*96;
        float vals[24];
        float s = 0.f, ss = 0.f;
        #pragma unroll
        for (int j = 0; j < 24; j++) {
            float v = xrow[l4 + 4*j];
            vals[j] = v; s += v; ss += v*v;
        }
        s  += __shfl_xor_sync(0xffffffffu, s, 1);
        s  += __shfl_xor_sync(0xffffffffu, s, 2);
        ss += __shfl_xor_sync(0xffffffffu, ss, 1);
        ss += __shfl_xor_sync(0xffffffffu, ss, 2);
        float mean = s * (1.f/96.f);
        float var  = ss * (1.f/96.f) - mean*mean;
        float rstd = rsqrtf(var + 1e-5f);
        #pragma unroll
        for (int j = 0; j < 24; j++) {
            int c = l4 + 4*j;
            xs[t*96 + c] = (vals[j]-mean)*rstd*g1[c] + bb1[c];
        }
    }
    __syncthreads();

    const int ty = tid >> 4, tx = tid & 15;
    const int t0 = ty*4, o0 = tx*6;

    // ---------- QKV: [64x96] @ [96x288] in 3 chunks of 96 ----------
    for (int s3 = 0; s3 < 3; s3++) {
        for (int e = tid; e < 96*96; e += 256) {
            int o = e / 96, kk = e - o*96;
            wb[kk*97 + o] = qkvw[s3*9216 + e];
        }
        __syncthreads();
        float acc[4][6];
        #pragma unroll
        for (int i=0;i<4;i++)
            #pragma unroll
            for (int j=0;j<6;j++) acc[i][j] = 0.f;
        for (int kk = 0; kk < 96; kk++) {
            float a[4], bv[6];
            #pragma unroll
            for (int i=0;i<4;i++) a[i] = xs[(t0+i)*96 + kk];
            #pragma unroll
            for (int j=0;j<6;j++) bv[j] = wb[kk*97 + o0 + j];
            #pragma unroll
            for (int i=0;i<4;i++)
                #pragma unroll
                for (int j=0;j<6;j++) acc[i][j] = fmaf(a[i], bv[j], acc[i][j]);
        }
        #pragma unroll
        for (int i=0;i<4;i++) {
            #pragma unroll
            for (int j=0;j<6;j++) {
                int ol = o0 + j;
                int h = ol >> 4, d = ol & 15;
                float v = acc[i][j] + qkvb[s3*96 + ol];
                if (s3 == 0) v *= 0.25f;   // q scale
                qkv[((s3*6 + h) << 10) + ((t0+i) << 4) + d] = v;
            }
        }
        __syncthreads();
    }

    // ---------- per-head attention ----------
    for (int h = 0; h < 6; h++) {
        const float* qh = qkv + h*1024;
        const float* kh = qkv + (6+h)*1024;
        const float* vh = qkv + (12+h)*1024;

        // scores + bias + mask
        for (int e = tid; e < 4096; e += 256) {
            int t = e >> 6, u = e & 63;
            const float* qp = qh + t*16;
            const float* kp = kh + u*16;
            float d = 0.f;
            #pragma unroll
            for (int z = 0; z < 16; z++) d = fmaf(qp[z], kp[z], d);
            int ti = t>>3, tj = t&7, ui = u>>3, uj = u&7;
            int ridx = (ti-ui+7)*15 + (tj-uj+7);
            d += __ldg(&rpb[ridx*6 + h]);
            if (shift) {
                int hrt = wh*8+ti, wrt = wwn*8+tj;
                int hru = wh*8+ui, wru = wwn*8+uj;
                int rt = (hrt<248?0:(hrt<252?1:2))*3 + (wrt<248?0:(wrt<252?1:2));
                int ru = (hru<248?0:(hru<252?1:2))*3 + (wru<248?0:(wru<252?1:2));
                if (rt != ru) d -= 100.f;
            }
            sc[t*64 + u] = d;
        }
        __syncthreads();

        // softmax: 4 lanes per row
        {
            int t = tid >> 2, l4 = tid & 3;
            float mx = -1e30f;
            #pragma unroll
            for (int j=0;j<16;j++) mx = fmaxf(mx, sc[t*64 + l4 + 4*j]);
            mx = fmaxf(mx, __shfl_xor_sync(0xffffffffu, mx, 1));
            mx = fmaxf(mx, __shfl_xor_sync(0xffffffffu, mx, 2));
            float sum = 0.f; float ev[16];
            #pragma unroll
            for (int j=0;j<16;j++) {
                float e2 = __expf(sc[t*64 + l4 + 4*j] - mx);
                ev[j] = e2; sum += e2;
            }
            sum += __shfl_xor_sync(0xffffffffu, sum, 1);
            sum += __shfl_xor_sync(0xffffffffu, sum, 2);
            float inv = 1.f / sum;
            #pragma unroll
            for (int j=0;j<16;j++) sc[t*64 + l4 + 4*j] = ev[j]*inv;
        }
        __syncthreads();

        // context = P @ V, written into xs (reused as [64 x 96] ctx)
        for (int e = tid; e < 1024; e += 256) {
            int t = e >> 4, d = e & 15;
            float a = 0.f;
            #pragma unroll
            for (int u = 0; u < 64; u++) a = fmaf(sc[t*64 + u], vh[u*16 + d], a);
            xs[t*96 + h*16 + d] = a;
        }
        __syncthreads();
    }

    // ---------- proj + residual ----------
    for (int e = tid; e < 96*96; e += 256) {
        int o = e / 96, kk = e - o*96;
        wb[kk*97 + o] = projw[e];
    }
    __syncthreads();
    {
        float acc[4][6];
        #pragma unroll
        for (int i=0;i<4;i++)
            #pragma unroll
            for (int j=0;j<6;j++) acc[i][j] = 0.f;
        for (int kk = 0; kk < 96; kk++) {
            float a[4], bv[6];
            #pragma unroll
            for (int i=0;i<4;i++) a[i] = xs[(t0+i)*96 + kk];
            #pragma unroll
            for (int j=0;j<6;j++) bv[j] = wb[kk*97 + o0 + j];
            #pragma unroll
            for (int i=0;i<4;i++)
                #pragma unroll
                for (int j=0;j<6;j++) acc[i][j] = fmaf(a[i], bv[j], acc[i][j]);
        }
        #pragma unroll
        for (int i=0;i<4;i++) {
            int t = t0 + i;
            int th = t>>3, tw = t&7;
            int h0 = (wh*8 + th + shift) & 255;
            int w0 = (wwn*8 + tw + shift) & 255;
            size_t row = ((size_t)b*65536 + (size_t)h0*256 + w0)*96;
            #pragma unroll
            for (int j=0;j<6;j++) {
                int o = o0 + j;
                xout[row + o] = xin[row + o] + acc[i][j] + projb[o];
            }
        }
    }
}

// -------------------- MLP kernel (64 tokens per block, in-place safe) --------------------
// smem layout: xs[64*96] | wb[96*97] | yb[64*96]
#define MLP_SMEM_FLOATS (6144 + 9312 + 6144)

__global__ void __launch_bounds__(256) mlp_kernel(
    const float* __restrict__ xin, float* __restrict__ xout,
    const float* __restrict__ g2, const float* __restrict__ bb2,
    const float* __restrict__ w1, const float* __restrict__ b1v,
    const float* __restrict__ w2, const float* __restrict__ b2v)
{
    extern __shared__ float sm[];
    float* xs = sm;            // 64x96 LN'd
    float* wb = sm + 6144;     // 96x97
    float* yb = sm + 6144 + 9312; // 64x96 gelu(fc1) chunk

    const int tid = threadIdx.x;
    const size_t base = (size_t)blockIdx.x * 64 * 96;

    // load + LN2
    {
        int t = tid >> 2, l4 = tid & 3;
        const float* xrow = xin + base + (size_t)t*96;
        float vals[24];
        float s = 0.f, ss = 0.f;
        #pragma unroll
        for (int j = 0; j < 24; j++) {
            float v = xrow[l4 + 4*j];
            vals[j] = v; s += v; ss += v*v;
        }
        s  += __shfl_xor_sync(0xffffffffu, s, 1);
        s  += __shfl_xor_sync(0xffffffffu, s, 2);
        ss += __shfl_xor_sync(0xffffffffu, ss, 1);
        ss += __shfl_xor_sync(0xffffffffu, ss, 2);
        float mean = s * (1.f/96.f);
        float var  = ss * (1.f/96.f) - mean*mean;
        float rstd = rsqrtf(var + 1e-5f);
        #pragma unroll
        for (int j = 0; j < 24; j++) {
            int c = l4 + 4*j;
            xs[t*96 + c] = (vals[j]-mean)*rstd*g2[c] + bb2[c];
        }
    }
    __syncthreads();

    const int ty = tid >> 4, tx = tid & 15;
    const int t0 = ty*4, c0 = tx*6;

    float oacc[4][6];
    #pragma unroll
    for (int i=0;i<4;i++)
        #pragma unroll
        for (int j=0;j<6;j++) oacc[i][j] = 0.f;

    for (int ch = 0; ch < 4; ch++) {
        // fc1 weight chunk, transposed into smem
        for (int e = tid; e < 96*96; e += 256) {
            int o = e / 96, kk = e - o*96;
            wb[kk*97 + o] = w1[ch*9216 + e];
        }
        __syncthreads();
        // y = gelu(xs @ w1_chunk^T + b1)
        {
            float acc[4][6];
            #pragma unroll
            for (int i=0;i<4;i++)
                #pragma unroll
                for (int j=0;j<6;j++) acc[i][j] = 0.f;
            for (int kk = 0; kk < 96; kk++) {
                float a[4], bv[6];
                #pragma unroll
                for (int i=0;i<4;i++) a[i] = xs[(t0+i)*96 + kk];
                #pragma unroll
                for (int j=0;j<6;j++) bv[j] = wb[kk*97 + c0 + j];
                #pragma unroll
                for (int i=0;i<4;i++)
                    #pragma unroll
                    for (int j=0;j<6;j++) acc[i][j] = fmaf(a[i], bv[j], acc[i][j]);
            }
            #pragma unroll
            for (int i=0;i<4;i++) {
                #pragma unroll
                for (int j=0;j<6;j++) {
                    float v = acc[i][j] + b1v[ch*96 + c0 + j];
                    yb[(t0+i)*96 + c0 + j] = v * normcdff(v);  // exact GELU
                }
            }
        }
        __syncthreads();
        // fc2 weight chunk: wb[oc][c] = w2[c][ch*96+oc]
        for (int e = tid; e < 96*96; e += 256) {
            int c = e / 96, oc = e - c*96;
            wb[oc*97 + c] = w2[(size_t)c*384 + ch*96 + oc];
        }
        __syncthreads();
        // oacc += yb @ w2_chunk
        for (int kk = 0; kk < 96; kk++) {
            float a[4], bv[6];
            #pragma unroll
            for (int i=0;i<4;i++) a[i] = yb[(t0+i)*96 + kk];
            #pragma unroll
            for (int j=0;j<6;j++) bv[j] = wb[kk*97 + c0 + j];
            #pragma unroll
            for (int i=0;i<4;i++)
                #pragma unroll
                for (int j=0;j<6;j++) oacc[i][j] = fmaf(a[i], bv[j], oacc[i][j]);
        }
        __syncthreads();
    }

    // residual write
    #pragma unroll
    for (int i=0;i<4;i++) {
        size_t row = base + (size_t)(t0+i)*96;
        #pragma unroll
        for (int j=0;j<6;j++) {
            int c = c0 + j;
            xout[row + c] = xin[row + c] + oacc[i][j] + b2v[c];
        }
    }
}

// -------------------- launcher --------------------
extern "C" void kernel_launch(void* const* d_in, const int* in_sizes, int n_in,
                              void* d_out, int out_size) {
    const float* x    = (const float*)d_in[0];
    const float* qkvw = (const float*)d_in[1];   // (2,288,96)
    const float* qkvb = (const float*)d_in[2];   // (2,288)
    const float* projw= (const float*)d_in[3];   // (2,96,96)
    const float* projb= (const float*)d_in[4];   // (2,96)
    const float* rpb  = (const float*)d_in[5];   // (2,225,6)
    const float* n1w  = (const float*)d_in[6];   // (2,96)
    const float* n1b  = (const float*)d_in[7];
    const float* n2w  = (const float*)d_in[8];
    const float* n2b  = (const float*)d_in[9];
    const float* f1w  = (const float*)d_in[10];  // (2,384,96)
    const float* f1b  = (const float*)d_in[11];  // (2,384)
    const float* f2w  = (const float*)d_in[12];  // (2,96,384)
    const float* f2b  = (const float*)d_in[13];  // (2,96)
    float* out = (float*)d_out;

    float* gx = nullptr;
    cudaGetSymbolAddress((void**)&gx, g_x);

    const int ATTN_SMEM = ATTN_SMEM_FLOATS * 4;
    const int MLP_SMEM  = MLP_SMEM_FLOATS * 4;
    cudaFuncSetAttribute(attn_kernel, cudaFuncAttributeMaxDynamicSharedMemorySize, ATTN_SMEM);
    cudaFuncSetAttribute(mlp_kernel,  cudaFuncAttributeMaxDynamicSharedMemorySize, MLP_SMEM);

    const int NBLK = 4096;   // 4 images * 1024 windows (= 262144 tokens / 64)

    // ---- block 0 (shift 0) ----
    attn_kernel<<<NBLK, 256, ATTN_SMEM>>>(x, out,
        qkvw, qkvb, projw, projb, rpb, n1w, n1b, 0);
    mlp_kernel<<<NBLK, 256, MLP_SMEM>>>(out, out,
        n2w, n2b, f1w, f1b, f2w, f2b);

    // ---- block 1 (shift 4) ----
    attn_kernel<<<NBLK, 256, ATTN_SMEM>>>(out, gx,
        qkvw + 288*96, qkvb + 288, projw + 96*96, projb + 96,
        rpb + 225*6, n1w + 96, n1b + 96, 4);
    mlp_kernel<<<NBLK, 256, MLP_SMEM>>>(gx, out,
        n2w + 96, n2b + 96, f1w + 384*96, f1b + 384, f2w + 96*384, f2b + 96);
}

// round 4
// speedup vs baseline: 2.2811x; 2.2811x over previous
#include <cuda_runtime.h>
#include <math.h>

// Swin stage: B=4, H=W=256, C=96, NH=6, HD=16, WS=8, N=64; 4096 windows.
// tf32 tensor-core version: all GEMMs via mma.sync.m16n8k8.tf32, weights
// pre-rounded to tf32 and packed in fragment order (one LDG.64 per B-frag).

#define X_ELEMS   (4*256*256*96)     // 25165824
#define W_ELEMS   221184             // packed tf32 weights, both layers

__device__ float g_x[X_ELEMS];       // ping-pong scratch
__device__ float g_w[W_ELEMS];       // packed tf32 weights

// packed-weight offsets (floats)
#define OFF_QKV0   0
#define OFF_QKV1   27648
#define OFF_PROJ0  55296
#define OFF_PROJ1  64512
#define OFF_F1_0   73728
#define OFF_F1_1   110592
#define OFF_F2_0   147456
#define OFF_F2_1   184320

__device__ __forceinline__ unsigned f2tf(float f) {
    unsigned u; asm("cvt.rna.tf32.f32 %0, %1;" : "=r"(u) : "f"(f)); return u;
}
__device__ __forceinline__ float tf32f(float f) {
    return __uint_as_float(f2tf(f));
}
__device__ __forceinline__ void mma_tf32(float* c, const unsigned* a, const unsigned* b) {
    asm volatile(
        "mma.sync.aligned.m16n8k8.row.col.f32.tf32.tf32.f32 "
        "{%0,%1,%2,%3},{%4,%5,%6,%7},{%8,%9},{%0,%1,%2,%3};\n"
        : "+f"(c[0]), "+f"(c[1]), "+f"(c[2]), "+f"(c[3])
        : "r"(a[0]), "r"(a[1]), "r"(a[2]), "r"(a[3]), "r"(b[0]), "r"(b[1]));
}

// ---- weight packer: W(O,K) row-major -> per-fragment tf32 layout ----
// B[k][n] = W[n][k]; packed[((nt*KS + kk)*32 + lane)*2 + j]
//   n = nt*8 + (lane>>2),  k = kk*8 + (lane&3) + j*4
__global__ void pack_w(const float* __restrict__ src, float* __restrict__ dst,
                       int O, int K) {
    int idx = blockIdx.x * 256 + threadIdx.x;
    if (idx >= O * K) return;
    int j    = idx & 1;
    int lane = (idx >> 1) & 31;
    int rest = idx >> 6;
    int KS   = K >> 3;
    int kk   = rest % KS;
    int nt   = rest / KS;
    int n = nt * 8 + (lane >> 2);
    int k = kk * 8 + (lane & 3) + j * 4;
    dst[idx] = __uint_as_float(f2tf(src[n * K + k]));
}

// ======================= attention kernel =======================
// smem (floats): xs[64*100]=6400 | qk[18*64*20]=23040 | sc[64*68]=4352
#define ATTN_SMEM_FLOATS (6400 + 23040 + 4352)

__global__ void __launch_bounds__(256) attn_kernel(
    const float* __restrict__ xin, float* __restrict__ xout,
    const float* __restrict__ wqkv, const float* __restrict__ qkvb,
    const float* __restrict__ wproj, const float* __restrict__ projb,
    const float* __restrict__ rpb,
    const float* __restrict__ g1, const float* __restrict__ bb1,
    int shift)
{
    extern __shared__ float sm[];
    float* xs = sm;           // 64 x 100 : LN'd x, later attention ctx
    float* qk = sm + 6400;    // [18][64][20] : q,k,v per head (tf32-rounded)
    float* sc = sm + 29440;   // 64 x 68 : scores / probs

    const int tid = threadIdx.x, lane = tid & 31, wid = tid >> 5;
    const int g = lane >> 2, tg = lane & 3;
    const int wm = wid >> 1, wn = wid & 1;
    const int m0 = wm * 16;

    const int win = blockIdx.x;
    const int b = win >> 10, wi = win & 1023, wh = wi >> 5, ww = wi & 31;

    // ---------- LN1 (4 threads/token), store tf32-rounded ----------
    {
        int t = tid >> 2, l4 = tid & 3;
        int th = t >> 3, tw = t & 7;
        int h0 = (wh*8 + th + shift) & 255, w0 = (ww*8 + tw + shift) & 255;
        const float* xr = xin + ((size_t)b*65536 + (size_t)h0*256 + w0)*96;
        float vals[24], s = 0.f, ss = 0.f;
        #pragma unroll
        for (int j = 0; j < 24; j++) {
            float v = xr[l4 + 4*j]; vals[j] = v; s += v; ss += v*v;
        }
        s  += __shfl_xor_sync(0xffffffffu, s, 1);
        s  += __shfl_xor_sync(0xffffffffu, s, 2);
        ss += __shfl_xor_sync(0xffffffffu, ss, 1);
        ss += __shfl_xor_sync(0xffffffffu, ss, 2);
        float mean = s * (1.f/96.f);
        float rstd = rsqrtf(ss * (1.f/96.f) - mean*mean + 1e-5f);
        #pragma unroll
        for (int j = 0; j < 24; j++) {
            int c = l4 + 4*j;
            xs[t*100 + c] = tf32f((vals[j]-mean)*rstd*g1[c] + bb1[c]);
        }
    }
    __syncthreads();

    // ---------- A fragments of xs (reused across all 3 qkv chunks) ----------
    unsigned Af[12][4];
    #pragma unroll
    for (int kk = 0; kk < 12; kk++) {
        int base = (m0+g)*100 + kk*8 + tg;
        Af[kk][0] = __float_as_uint(xs[base]);
        Af[kk][1] = __float_as_uint(xs[base + 800]);
        Af[kk][2] = __float_as_uint(xs[base + 4]);
        Af[kk][3] = __float_as_uint(xs[base + 804]);
    }

    // ---------- QKV GEMM: 3 chunks of 96 outputs ----------
    for (int s3 = 0; s3 < 3; s3++) {
        float acc[6][4];
        #pragma unroll
        for (int i = 0; i < 6; i++) { acc[i][0]=acc[i][1]=acc[i][2]=acc[i][3]=0.f; }
        for (int kk = 0; kk < 12; kk++) {
            #pragma unroll
            for (int nt = 0; nt < 6; nt++) {
                int ntg = s3*12 + wn*6 + nt;
                float2 bv = *(const float2*)&wqkv[((ntg*12 + kk)*32 + lane)*2];
                unsigned bb[2] = { __float_as_uint(bv.x), __float_as_uint(bv.y) };
                mma_tf32(acc[nt], Af[kk], bb);
            }
        }
        #pragma unroll
        for (int nt = 0; nt < 6; nt++) {
            #pragma unroll
            for (int i = 0; i < 2; i++) {
                #pragma unroll
                for (int j = 0; j < 2; j++) {
                    int ncol = wn*48 + nt*8 + 2*tg + j;
                    int hh = ncol >> 4, d = ncol & 15;
                    int m = m0 + g + i*8;
                    float v = acc[nt][i*2+j] + __ldg(&qkvb[s3*96 + ncol]);
                    if (s3 == 0) v *= 0.25f;
                    qk[(s3*6 + hh)*1280 + m*20 + d] = tf32f(v);
                }
            }
        }
    }
    __syncthreads();

    // ---------- per-head attention ----------
    for (int h = 0; h < 6; h++) {
        const float* qh = qk + h*1280;
        const float* kh = qk + (6+h)*1280;
        const float* vh = qk + (12+h)*1280;

        // scores: warp tile [m0,m0+16) x [wn*32, wn*32+32)
        {
            unsigned Aq[2][4];
            #pragma unroll
            for (int kk = 0; kk < 2; kk++) {
                int base = (m0+g)*20 + kk*8 + tg;
                Aq[kk][0] = __float_as_uint(qh[base]);
                Aq[kk][1] = __float_as_uint(qh[base + 160]);
                Aq[kk][2] = __float_as_uint(qh[base + 4]);
                Aq[kk][3] = __float_as_uint(qh[base + 164]);
            }
            float acc[4][4];
            #pragma unroll
            for (int i = 0; i < 4; i++) { acc[i][0]=acc[i][1]=acc[i][2]=acc[i][3]=0.f; }
            #pragma unroll
            for (int kk = 0; kk < 2; kk++) {
                #pragma unroll
                for (int nt = 0; nt < 4; nt++) {
                    int u0 = wn*32 + nt*8;
                    unsigned bb[2] = {
                        __float_as_uint(kh[(u0+g)*20 + kk*8 + tg]),
                        __float_as_uint(kh[(u0+g)*20 + kk*8 + tg + 4]) };
                    mma_tf32(acc[nt], Aq[kk], bb);
                }
            }
            #pragma unroll
            for (int nt = 0; nt < 4; nt++) {
                #pragma unroll
                for (int i = 0; i < 2; i++) {
                    #pragma unroll
                    for (int j = 0; j < 2; j++) {
                        int t = m0 + g + i*8;
                        int u = wn*32 + nt*8 + 2*tg + j;
                        int ti = t>>3, tj = t&7, ui = u>>3, uj = u&7;
                        float d = acc[nt][i*2+j]
                                + __ldg(&rpb[((ti-ui+7)*15 + (tj-uj+7))*6 + h]);
                        if (shift) {
                            int hrt = wh*8+ti, wrt = ww*8+tj;
                            int hru = wh*8+ui, wru = ww*8+uj;
                            int rt = (hrt<248?0:(hrt<252?1:2))*3 + (wrt<248?0:(wrt<252?1:2));
                            int ru = (hru<248?0:(hru<252?1:2))*3 + (wru<248?0:(wru<252?1:2));
                            if (rt != ru) d -= 100.f;
                        }
                        sc[t*68 + u] = d;
                    }
                }
            }
        }
        __syncthreads();

        // softmax (fp32), store tf32-rounded probs
        {
            int t = tid >> 2, l4 = tid & 3;
            float mx = -1e30f;
            #pragma unroll
            for (int j = 0; j < 16; j++) mx = fmaxf(mx, sc[t*68 + l4 + 4*j]);
            mx = fmaxf(mx, __shfl_xor_sync(0xffffffffu, mx, 1));
            mx = fmaxf(mx, __shfl_xor_sync(0xffffffffu, mx, 2));
            float ev[16], sum = 0.f;
            #pragma unroll
            for (int j = 0; j < 16; j++) {
                float e = __expf(sc[t*68 + l4 + 4*j] - mx);
                ev[j] = e; sum += e;
            }
            sum += __shfl_xor_sync(0xffffffffu, sum, 1);
            sum += __shfl_xor_sync(0xffffffffu, sum, 2);
            float inv = 1.f / sum;
            #pragma unroll
            for (int j = 0; j < 16; j++) sc[t*68 + l4 + 4*j] = tf32f(ev[j]*inv);
        }
        __syncthreads();

        // AV: warp tile [m0,m0+16) x [wn*8, wn*8+8), K=64
        {
            float acc[4] = {0.f, 0.f, 0.f, 0.f};
            int n0 = wn * 8;
            #pragma unroll
            for (int kk = 0; kk < 8; kk++) {
                int base = (m0+g)*68 + kk*8 + tg;
                unsigned Ap[4] = {
                    __float_as_uint(sc[base]),
                    __float_as_uint(sc[base + 544]),
                    __float_as_uint(sc[base + 4]),
                    __float_as_uint(sc[base + 548]) };
                unsigned bb[2] = {
                    __float_as_uint(vh[(kk*8+tg)*20 + n0 + g]),
                    __float_as_uint(vh[(kk*8+tg+4)*20 + n0 + g]) };
                mma_tf32(acc, Ap, bb);
            }
            #pragma unroll
            for (int i = 0; i < 2; i++)
                #pragma unroll
                for (int j = 0; j < 2; j++)
                    xs[(m0+g+i*8)*100 + h*16 + n0 + 2*tg + j] = tf32f(acc[i*2+j]);
        }
        __syncthreads();
    }

    // ---------- proj + residual ----------
    {
        unsigned Ac[12][4];
        #pragma unroll
        for (int kk = 0; kk < 12; kk++) {
            int base = (m0+g)*100 + kk*8 + tg;
            Ac[kk][0] = __float_as_uint(xs[base]);
            Ac[kk][1] = __float_as_uint(xs[base + 800]);
            Ac[kk][2] = __float_as_uint(xs[base + 4]);
            Ac[kk][3] = __float_as_uint(xs[base + 804]);
        }
        float acc[6][4];
        #pragma unroll
        for (int i = 0; i < 6; i++) { acc[i][0]=acc[i][1]=acc[i][2]=acc[i][3]=0.f; }
        for (int kk = 0; kk < 12; kk++) {
            #pragma unroll
            for (int nt = 0; nt < 6; nt++) {
                int ntg = wn*6 + nt;
                float2 bv = *(const float2*)&wproj[((ntg*12 + kk)*32 + lane)*2];
                unsigned bb[2] = { __float_as_uint(bv.x), __float_as_uint(bv.y) };
                mma_tf32(acc[nt], Ac[kk], bb);
            }
        }
        #pragma unroll
        for (int nt = 0; nt < 6; nt++) {
            #pragma unroll
            for (int i = 0; i < 2; i++) {
                int ncol0 = wn*48 + nt*8 + 2*tg;
                int m = m0 + g + i*8;
                int th = m >> 3, tw = m & 7;
                int h0 = (wh*8 + th + shift) & 255;
                int w0 = (ww*8 + tw + shift) & 255;
                size_t row = ((size_t)b*65536 + (size_t)h0*256 + w0)*96;
                float2 r = *(const float2*)&xin[row + ncol0];
                float2 o;
                o.x = r.x + acc[nt][i*2]   + __ldg(&projb[ncol0]);
                o.y = r.y + acc[nt][i*2+1] + __ldg(&projb[ncol0+1]);
                *(float2*)&xout[row + ncol0] = o;
            }
        }
    }
}

// ======================= MLP kernel =======================
// smem: xs[64*100]=6400 | yb[64*100]=6400
#define MLP_SMEM_FLOATS (6400 + 6400)

__global__ void __launch_bounds__(256, 2) mlp_kernel(
    const float* __restrict__ xin, float* __restrict__ xout,
    const float* __restrict__ g2, const float* __restrict__ bb2,
    const float* __restrict__ w1p, const float* __restrict__ b1v,
    const float* __restrict__ w2p, const float* __restrict__ b2v)
{
    extern __shared__ float sm[];
    float* xs = sm;          // 64 x 100 LN'd (tf32)
    float* yb = sm + 6400;   // 64 x 100 gelu(fc1) chunk (tf32)

    const int tid = threadIdx.x, lane = tid & 31, wid = tid >> 5;
    const int g = lane >> 2, tg = lane & 3;
    const int wm = wid >> 1, wn = wid & 1;
    const int m0 = wm * 16;
    const size_t base = (size_t)blockIdx.x * 64 * 96;

    // LN2
    {
        int t = tid >> 2, l4 = tid & 3;
        const float* xr = xin + base + (size_t)t*96;
        float vals[24], s = 0.f, ss = 0.f;
        #pragma unroll
        for (int j = 0; j < 24; j++) {
            float v = xr[l4 + 4*j]; vals[j] = v; s += v; ss += v*v;
        }
        s  += __shfl_xor_sync(0xffffffffu, s, 1);
        s  += __shfl_xor_sync(0xffffffffu, s, 2);
        ss += __shfl_xor_sync(0xffffffffu, ss, 1);
        ss += __shfl_xor_sync(0xffffffffu, ss, 2);
        float mean = s * (1.f/96.f);
        float rstd = rsqrtf(ss * (1.f/96.f) - mean*mean + 1e-5f);
        #pragma unroll
        for (int j = 0; j < 24; j++) {
            int c = l4 + 4*j;
            xs[t*100 + c] = tf32f((vals[j]-mean)*rstd*g2[c] + bb2[c]);
        }
    }
    __syncthreads();

    unsigned Af[12][4];
    #pragma unroll
    for (int kk = 0; kk < 12; kk++) {
        int bse = (m0+g)*100 + kk*8 + tg;
        Af[kk][0] = __float_as_uint(xs[bse]);
        Af[kk][1] = __float_as_uint(xs[bse + 800]);
        Af[kk][2] = __float_as_uint(xs[bse + 4]);
        Af[kk][3] = __float_as_uint(xs[bse + 804]);
    }

    float acc2[6][4];
    #pragma unroll
    for (int i = 0; i < 6; i++) { acc2[i][0]=acc2[i][1]=acc2[i][2]=acc2[i][3]=0.f; }

    for (int ch = 0; ch < 4; ch++) {
        // fc1 chunk
        float acc[6][4];
        #pragma unroll
        for (int i = 0; i < 6; i++) { acc[i][0]=acc[i][1]=acc[i][2]=acc[i][3]=0.f; }
        for (int kk = 0; kk < 12; kk++) {
            #pragma unroll
            for (int nt = 0; nt < 6; nt++) {
                int ntg = ch*12 + wn*6 + nt;
                float2 bv = *(const float2*)&w1p[((ntg*12 + kk)*32 + lane)*2];
                unsigned bb[2] = { __float_as_uint(bv.x), __float_as_uint(bv.y) };
                mma_tf32(acc[nt], Af[kk], bb);
            }
        }
        // gelu -> yb
        #pragma unroll
        for (int nt = 0; nt < 6; nt++) {
            #pragma unroll
            for (int i = 0; i < 2; i++) {
                #pragma unroll
                for (int j = 0; j < 2; j++) {
                    int c = wn*48 + nt*8 + 2*tg + j;
                    float v = acc[nt][i*2+j] + __ldg(&b1v[ch*96 + c]);
                    v = v * normcdff(v);
                    yb[(m0+g+i*8)*100 + c] = tf32f(v);
                }
            }
        }
        __syncthreads();
        // fc2 partial accumulate
        for (int kk = 0; kk < 12; kk++) {
            int bse = (m0+g)*100 + kk*8 + tg;
            unsigned Ay[4] = {
                __float_as_uint(yb[bse]),
                __float_as_uint(yb[bse + 800]),
                __float_as_uint(yb[bse + 4]),
                __float_as_uint(yb[bse + 804]) };
            #pragma unroll
            for (int nt = 0; nt < 6; nt++) {
                int ntg = wn*6 + nt;
                int kkg = ch*12 + kk;
                float2 bv = *(const float2*)&w2p[((ntg*48 + kkg)*32 + lane)*2];
                unsigned bb[2] = { __float_as_uint(bv.x), __float_as_uint(bv.y) };
                mma_tf32(acc2[nt], Ay, bb);
            }
        }
        __syncthreads();
    }

    // residual writeback
    #pragma unroll
    for (int nt = 0; nt < 6; nt++) {
        #pragma unroll
        for (int i = 0; i < 2; i++) {
            int c0 = wn*48 + nt*8 + 2*tg;
            int m = m0 + g + i*8;
            float2 r = *(const float2*)&xin[base + (size_t)m*96 + c0];
            float2 o;
            o.x = r.x + acc2[nt][i*2]   + __ldg(&b2v[c0]);
            o.y = r.y + acc2[nt][i*2+1] + __ldg(&b2v[c0+1]);
            *(float2*)&xout[base + (size_t)m*96 + c0] = o;
        }
    }
}

// ======================= launcher =======================
extern "C" void kernel_launch(void* const* d_in, const int* in_sizes, int n_in,
                              void* d_out, int out_size) {
    const float* x    = (const float*)d_in[0];
    const float* qkvw = (const float*)d_in[1];   // (2,288,96)
    const float* qkvb = (const float*)d_in[2];   // (2,288)
    const float* projw= (const float*)d_in[3];   // (2,96,96)
    const float* projb= (const float*)d_in[4];   // (2,96)
    const float* rpb  = (const float*)d_in[5];   // (2,225,6)
    const float* n1w  = (const float*)d_in[6];
    const float* n1b  = (const float*)d_in[7];
    const float* n2w  = (const float*)d_in[8];
    const float* n2b  = (const float*)d_in[9];
    const float* f1w  = (const float*)d_in[10];  // (2,384,96)
    const float* f1b  = (const float*)d_in[11];  // (2,384)
    const float* f2w  = (const float*)d_in[12];  // (2,96,384)
    const float* f2b  = (const float*)d_in[13];  // (2,96)
    float* out = (float*)d_out;

    float* gx = nullptr;  cudaGetSymbolAddress((void**)&gx, g_x);
    float* gw = nullptr;  cudaGetSymbolAddress((void**)&gw, g_w);

    // ---- pack weights to tf32 fragment order ----
    pack_w<<<108, 256>>>(qkvw,          gw + OFF_QKV0, 288, 96);
    pack_w<<<108, 256>>>(qkvw + 27648,  gw + OFF_QKV1, 288, 96);
    pack_w<<<36,  256>>>(projw,         gw + OFF_PROJ0, 96, 96);
    pack_w<<<36,  256>>>(projw + 9216,  gw + OFF_PROJ1, 96, 96);
    pack_w<<<144, 256>>>(f1w,           gw + OFF_F1_0, 384, 96);
    pack_w<<<144, 256>>>(f1w + 36864,   gw + OFF_F1_1, 384, 96);
    pack_w<<<144, 256>>>(f2w,           gw + OFF_F2_0, 96, 384);
    pack_w<<<144, 256>>>(f2w + 36864,   gw + OFF_F2_1, 96, 384);

    const int ATTN_SMEM = ATTN_SMEM_FLOATS * 4;   // 135168 B
    const int MLP_SMEM  = MLP_SMEM_FLOATS * 4;    // 51200 B
    cudaFuncSetAttribute(attn_kernel, cudaFuncAttributeMaxDynamicSharedMemorySize, ATTN_SMEM);
    cudaFuncSetAttribute(mlp_kernel,  cudaFuncAttributeMaxDynamicSharedMemorySize, MLP_SMEM);

    const int NBLK = 4096;

    // ---- block 0 (shift 0) ----
    attn_kernel<<<NBLK, 256, ATTN_SMEM>>>(x, out,
        gw + OFF_QKV0, qkvb, gw + OFF_PROJ0, projb, rpb, n1w, n1b, 0);
    mlp_kernel<<<NBLK, 256, MLP_SMEM>>>(out, out,
        n2w, n2b, gw + OFF_F1_0, f1b, gw + OFF_F2_0, f2b);

    // ---- block 1 (shift 4) ----
    attn_kernel<<<NBLK, 256, ATTN_SMEM>>>(out, gx,
        gw + OFF_QKV1, qkvb + 288, gw + OFF_PROJ1, projb + 96,
        rpb + 225*6, n1w + 96, n1b + 96, 4);
    mlp_kernel<<<NBLK, 256, MLP_SMEM>>>(gx, out,
        n2w + 96, n2b + 96, gw + OFF_F1_1, f1b + 384, gw + OFF_F2_1, f2b + 96);
}